// round 10
// baseline (speedup 1.0000x reference)
#include <cuda_runtime.h>

// DisplacementMap (tfa dense_image_warp) — B=8, H=512, W=512, C=16, fp32.
// R5: column-marching CTAs for L1 gather-reuse capture.
// Model: kernel is L2(LTS)-throughput bound (~6700 B/cyc chip-wide). Each
// x-chunk (64B) is gathered ~4x by output pixels spread over a +-15 row/col
// window; with row-linear CTAs that reuse all misses to L2. A CTA that owns a
// 64-px-wide column and marches down 64 rows keeps its ~31-row gather band
// (~186KB) resident in L1 (228KB), converting most reuse into L1 hits and
// cutting L2 volume ~40%.

#define H_DIM 512
#define W_DIM 512
#define C_DIM 16
#define B_DIM 8

#define W_TILE 64          // column width in pixels
#define SEG_ROWS 64        // rows marched per CTA
#define ROWS_PER_ITER 2    // 512 threads / (64 px * 4 lanes)
#define N_ITERS (SEG_ROWS / ROWS_PER_ITER)   // 32

__global__ __launch_bounds__(512) void displacement_map_kernel(
    const float* __restrict__ x,
    const float* __restrict__ flow,
    float* __restrict__ out)
{
    // CTA id -> (w-tile, h-segment, batch)
    const int bw = blockIdx.x & 7;          // 8 w-tiles
    const int hs = (blockIdx.x >> 3) & 7;   // 8 h-segments
    const int bb = blockIdx.x >> 6;         // 8 batches

    const int t       = threadIdx.x;
    const int cg      = t & 3;              // channel group (4 floats)
    const int px      = (t >> 2) & 63;      // pixel within 64-wide column
    const int row_sub = t >> 8;             // 0 or 1

    const int w = bw * W_TILE + px;
    const int h_base = hs * SEG_ROWS + row_sub;

    const float4* __restrict__ xf4 = reinterpret_cast<const float4*>(x);
    const float2* __restrict__ fl2 = reinterpret_cast<const float2*>(flow);
    float4* __restrict__ of4 = reinterpret_cast<float4*>(out);

    const size_t row_stride_f4 = (size_t)W_DIM * C_DIM / 4;  // 2048
    const size_t batch_base = (size_t)bb * H_DIM;            // in rows

    #pragma unroll 1
    for (int it = 0; it < N_ITERS; ++it) {
        const int h = h_base + it * ROWS_PER_ITER;
        const int pix = ((bb << 9) + h) * W_DIM + w;   // ((b*H + h)*W + w)

        const float2 f = fl2[pix];

        const float qy = (float)h - f.x;
        const float qx = (float)w - f.y;

        float fy = fminf(fmaxf(floorf(qy), 0.0f), (float)(H_DIM - 2));
        float fx = fminf(fmaxf(floorf(qx), 0.0f), (float)(W_DIM - 2));
        const float ay = fminf(fmaxf(qy - fy, 0.0f), 1.0f);
        const float ax = fminf(fmaxf(qx - fx, 0.0f), 1.0f);
        const int iy = (int)fy;
        const int ix = (int)fx;

        const size_t base_f4 =
            (((batch_base + (size_t)iy) * W_DIM + (size_t)ix) * C_DIM) >> 2;

        // Four gathers; default caching so they allocate in L1 (we want the
        // band resident).
        const float4 tl = xf4[base_f4 + cg];
        const float4 tr = xf4[base_f4 + cg + (C_DIM / 4)];
        const float4 bl = xf4[base_f4 + cg + row_stride_f4];
        const float4 br = xf4[base_f4 + cg + row_stride_f4 + (C_DIM / 4)];

        float4 r;
        {
            float tt, bb2;
            tt = tl.x + ax * (tr.x - tl.x);  bb2 = bl.x + ax * (br.x - bl.x);
            r.x = tt + ay * (bb2 - tt);
            tt = tl.y + ax * (tr.y - tl.y);  bb2 = bl.y + ax * (br.y - bl.y);
            r.y = tt + ay * (bb2 - tt);
            tt = tl.z + ax * (tr.z - tl.z);  bb2 = bl.z + ax * (br.z - bl.z);
            r.z = tt + ay * (bb2 - tt);
            tt = tl.w + ax * (tr.w - tl.w);  bb2 = bl.w + ax * (br.w - bl.w);
            r.w = tt + ay * (bb2 - tt);
        }

        // Streaming store (don't displace the gather band from L1).
        __stcs(of4 + ((size_t)pix * 4 + cg), r);

        // Keep the CTA's warps marching together so the L1 band window stays
        // tight (barrier cost ~47cyc/iter is negligible).
        __syncthreads();
    }
}

extern "C" void kernel_launch(void* const* d_in, const int* in_sizes, int n_in,
                              void* d_out, int out_size)
{
    const float* x    = (const float*)d_in[0];
    const float* flow = (const float*)d_in[1];
    float* out        = (float*)d_out;

    // 8 w-tiles * 8 h-segments * 8 batches = 512 CTAs of 512 threads
    displacement_map_kernel<<<512, 512>>>(x, flow, out);
}